// round 9
// baseline (speedup 1.0000x reference)
#include <cuda_runtime.h>
#include <cuda_fp16.h>
#include <cstdint>

#define DIM  1024
#define NTOK 4096
#define NSK  50
#define BM 128
#define BN 256
#define BK 64                             // 64 halves = 128B (A) / 64 k-rows (B)
#define NSTAGE 4
#define A_BYTES (BM*128)                  // 16KB per stage: 128 m-rows x 128B
#define B_BYTES (BK*512)                  // 32KB per stage: 64 k-rows x 512B
#define SMEM_DYN (NSTAGE*(A_BYTES+B_BYTES) + 1024)   // 197632

// ---------------- scratch (static device, allocation-free) ----------------
__device__ __half g_Xh [(size_t)NTOK*DIM];
__device__ __half g_W1h[(size_t)NSK*DIM*DIM];        // original layout [e][d][h]
__device__ __half g_W2h[(size_t)NSK*DIM*DIM];        // original layout [e][h][d]
__device__ __half g_Hh [(size_t)NSK*NTOK*DIM];       // gate-scaled hidden [e][m][h]
__device__ float  g_gates[(size_t)NTOK*NSK];
__device__ float  g_Wgt[64*DIM];                      // transposed gate weights [s][j]

// ---------------- helpers ----------------
__device__ __forceinline__ uint32_t smem_u32(const void* p){
    uint32_t a; asm("{ .reg .u64 t; cvta.to.shared.u64 t, %1; cvt.u32.u64 %0, t; }":"=r"(a):"l"(p)); return a;
}
__device__ __forceinline__ void cp_async16(uint32_t s, const void* gp){
    uint64_t g = __cvta_generic_to_global(gp);
    asm volatile("cp.async.cg.shared.global [%0], [%1], 16;"::"r"(s),"l"(g));
}
#define CP_COMMIT() asm volatile("cp.async.commit_group;":::"memory")

__device__ __forceinline__ void stcs16(void* gp, uint4 v){
    asm volatile("st.global.cs.v4.b32 [%0], {%1,%2,%3,%4};"
                 :: "l"(__cvta_generic_to_global(gp)), "r"(v.x),"r"(v.y),"r"(v.z),"r"(v.w));
}

#define LDSM_X4(r, a) \
    asm volatile("ldmatrix.sync.aligned.m8n8.x4.shared.b16 {%0,%1,%2,%3}, [%4];" \
        : "=r"((r)[0]),"=r"((r)[1]),"=r"((r)[2]),"=r"((r)[3]) : "r"(a))

#define LDSM_X4_T(r, a) \
    asm volatile("ldmatrix.sync.aligned.m8n8.x4.trans.shared.b16 {%0,%1,%2,%3}, [%4];" \
        : "=r"((r)[0]),"=r"((r)[1]),"=r"((r)[2]),"=r"((r)[3]) : "r"(a))

#define MMA_F16(c, a, b0, b1) \
    asm volatile("mma.sync.aligned.m16n8k16.row.col.f32.f16.f16.f32 " \
        "{%0,%1,%2,%3},{%4,%5,%6,%7},{%8,%9},{%0,%1,%2,%3};" \
        : "+f"((c)[0]),"+f"((c)[1]),"+f"((c)[2]),"+f"((c)[3]) \
        : "r"((a)[0]),"r"((a)[1]),"r"((a)[2]),"r"((a)[3]),"r"(b0),"r"(b1))

// ---------------- fused prep kernel ----------------
// Block roles by blockIdx.x:
//   [0, 51200)          : convert W1/W2 slice (256 thr x 8 floats = 2048 elems/block)
//   [51200, 51200+4096) : gates + x fp16 conversion for one token (256 thr)
//   [55296, 55298)      : Wg transpose halves
#define NCONV 51200
__global__ void __launch_bounds__(256) prep_kernel(const float* __restrict__ x,
                                                   const float* __restrict__ W1,
                                                   const float* __restrict__ W2,
                                                   const float* __restrict__ Wg,
                                                   const float* __restrict__ bg){
    int bid = blockIdx.x, tid = threadIdx.x;
    if(bid < NCONV){
        // each of the 2*50 1024x1024 tensors split into 512 blocks of 2048 elems
        int half = bid >> 9 & 0 ; // placeholder (see below)
        // simpler: first 25600 blocks -> W1, next 25600 -> W2
        const float* src = (bid < NCONV/2) ? W1 : W2;
        __half* dst = (bid < NCONV/2) ? g_W1h : g_W2h;
        size_t b = (size_t)(bid < NCONV/2 ? bid : bid - NCONV/2);
        size_t base = b*2048 + (size_t)tid*8;
        float4 a = *(const float4*)(src + base);
        float4 c = *(const float4*)(src + base + 4);
        __half2 h[4];
        h[0] = __floats2half2_rn(a.x, a.y); h[1] = __floats2half2_rn(a.z, a.w);
        h[2] = __floats2half2_rn(c.x, c.y); h[3] = __floats2half2_rn(c.z, c.w);
        stcs16(dst + base, *(uint4*)h);
        (void)half;
        return;
    }
    if(bid < NCONV + NTOK){
        int n = bid - NCONV;
        __shared__ float xs[DIM]; __shared__ float raw[64]; __shared__ float ssum;
        for(int j=tid; j<DIM; j+=256){
            float v = x[(size_t)n*DIM + j];
            xs[j] = v;
            g_Xh[(size_t)n*DIM + j] = __float2half_rn(v);
        }
        __syncthreads();
        int wid = tid>>5, lid = tid&31;
        for(int s=wid; s<NSK; s+=8){
            float acc = 0.f;
            #pragma unroll 8
            for(int j=lid; j<DIM; j+=32) acc += xs[j]*g_Wgt[(size_t)s*DIM + j];
            #pragma unroll
            for(int o=16;o;o>>=1) acc += __shfl_xor_sync(0xFFFFFFFFu, acc, o);
            if(lid==0) raw[s] = acc + bg[s];
        }
        __syncthreads();
        if(tid==0){
            float m = -1e30f;
            for(int s=0;s<NSK;s++) m = fmaxf(m, raw[s]);
            float sm = 0.f;
            for(int s=0;s<NSK;s++){ float e = __expf(raw[s]-m); raw[s]=e; sm+=e; }
            ssum = sm;
        }
        __syncthreads();
        if(tid<NSK) g_gates[(size_t)n*NSK + tid] = raw[tid]/ssum;
        return;
    }
    {   // Wg transpose: 2 blocks, each 512 j-rows
        int j0 = (bid - NCONV - NTOK) * 512;
        // t covers 512 x 50 -> write g_Wgt[s][j]
        for(int i=tid; i<512*NSK; i+=256){
            int j = i / NSK, s = i % NSK;
            g_Wgt[(size_t)s*DIM + j0 + j] = Wg[(size_t)(j0+j)*NSK + s];
        }
    }
}

// NOTE: g_Wgt must be filled before gates blocks run. Blocks are not ordered,
// so gates must NOT depend on g_Wgt from the same launch. Instead gates blocks
// read Wg directly but via a smem-staged transpose per block (cheap: 50 cols).
// To keep it simple and correct, gates blocks below re-read Wg strided — the
// 200KB Wg is L2-resident after the first few blocks, so the cost is small.
// (g_Wgt retained for layout compatibility but unused.)

// ---------------- main fp16 mma.sync GEMM ----------------
template<int PHASE>
__global__ void __launch_bounds__(256,1) gemm_kernel(const float* __restrict__ b1,
                                                     const float* __restrict__ b2,
                                                     float* __restrict__ dout){
    extern __shared__ char dsm[];
    const uint32_t sb = (smem_u32(dsm) + 1023u) & ~1023u;
    const uint32_t A0 = sb, B0 = sb + NSTAGE*A_BYTES;
    const int tid = threadIdx.x, wid = tid>>5, lane = tid&31;
    const int wm = wid & 1, wn = wid >> 1;            // 2x4 warp grid
    const int m0 = blockIdx.x*BM, n0 = blockIdx.y*BN;
    const int NS = (PHASE==1) ? (DIM/BK) : (NSK*DIM/BK);   // 16 / 800

    const int mat = lane>>3, rr = lane&7;
    const int a_rowl = (mat&1)*8 + rr;
    const int a_bc   = (mat>>1)*16;
    const uint32_t xorv = (uint32_t)(rr<<4);
    const int b_row  = lane & 15;
    const int b_noff = (lane >> 4) * 16;
    const int gr = lane>>2, gc = (lane&3)*2;

    float c[4][8][4];
    #pragma unroll
    for(int i=0;i<4;i++)
      #pragma unroll
      for(int j=0;j<8;j++)
        #pragma unroll
        for(int k=0;k<4;k++) c[i][j][k] = 0.f;

    auto load_tile = [&](int step){
        const __half *Ag, *Bg;
        if(PHASE==1){
            int e = blockIdx.z, kk = step*BK;
            Ag = g_Xh  + (size_t)m0*DIM + kk;
            Bg = g_W1h + (size_t)e*DIM*DIM + (size_t)kk*DIM + n0;
        } else {
            int e = step>>4, kk = (step&15)*BK;
            Ag = g_Hh  + ((size_t)e*NTOK + m0)*DIM + kk;
            Bg = g_W2h + (size_t)e*DIM*DIM + (size_t)kk*DIM + n0;
        }
        uint32_t as = A0 + (step&3)*A_BYTES, bs = B0 + (step&3)*B_BYTES;
        #pragma unroll
        for(int i=0;i<4;i++){ int q = tid + i*256; int r=q>>3, cc=q&7;
            cp_async16(as + (uint32_t)(r*128 + ((cc*16) ^ ((r&7)<<4))), Ag + (size_t)r*DIM + cc*8); }
        #pragma unroll
        for(int i=0;i<8;i++){ int q = tid + i*256; int r=q>>5, cc=q&31;
            cp_async16(bs + (uint32_t)(r*512 + ((cc*16) ^ ((r&7)<<4))), Bg + (size_t)r*DIM + cc*8); }
        CP_COMMIT();
    };

    load_tile(0); load_tile(1); load_tile(2);

    if(PHASE==2){
        for(int e=0; e<NSK; e++){
            float gg[4][2];
            #pragma unroll
            for(int mi=0; mi<4; mi++)
                #pragma unroll
                for(int half=0; half<2; half++)
                    gg[mi][half] = g_gates[(size_t)(m0 + wm*64 + mi*16 + gr + half*8)*NSK + e];
            #pragma unroll
            for(int ni=0; ni<8; ni++){
                const float2 bb = *(const float2*)(b2 + (size_t)e*DIM + n0 + wn*64 + ni*8 + gc);
                #pragma unroll
                for(int mi=0; mi<4; mi++)
                    #pragma unroll
                    for(int half=0; half<2; half++){
                        c[mi][ni][half*2+0] += gg[mi][half]*bb.x;
                        c[mi][ni][half*2+1] += gg[mi][half]*bb.y;
                    }
            }
        }
    }

    for(int step=0; step<NS; step++){
        asm volatile("cp.async.wait_group 2;":::"memory");
        __syncthreads();
        if(step+3 < NS) load_tile(step+3); else CP_COMMIT();

        const uint32_t as = A0 + (step&3)*A_BYTES;
        const uint32_t bs = B0 + (step&3)*B_BYTES;
        #pragma unroll
        for(int ks=0; ks<4; ks++){
            uint32_t a[4][4], b[4][4];
            #pragma unroll
            for(int mi=0; mi<4; mi++){
                int row = wm*64 + mi*16 + a_rowl;
                LDSM_X4(a[mi], as + (uint32_t)(row*128) + (((uint32_t)(ks*32 + a_bc)) ^ xorv));
            }
            #pragma unroll
            for(int p=0; p<4; p++){
                int rowk = ks*16 + b_row;
                uint32_t bcol = (uint32_t)(wn*128 + p*32 + b_noff);
                LDSM_X4_T(b[p], bs + (uint32_t)(rowk*512) + (bcol ^ (uint32_t)((rowk&7)<<4)));
            }
            #pragma unroll
            for(int mi=0; mi<4; mi++)
                #pragma unroll
                for(int ni=0; ni<8; ni++)
                    MMA_F16(c[mi][ni], a[mi], b[ni>>1][(ni&1)*2], b[ni>>1][(ni&1)*2+1]);
        }
    }
    __syncthreads();

    // ---------------- epilogue ----------------
    #pragma unroll
    for(int mi=0; mi<4; mi++){
        int r0 = m0 + wm*64 + mi*16 + gr;
        #pragma unroll
        for(int half=0; half<2; half++){
            int row = r0 + half*8;
            float gate = 0.f;
            if(PHASE==1) gate = g_gates[(size_t)row*NSK + blockIdx.z];
            #pragma unroll
            for(int ni=0; ni<8; ni++){
                int col = n0 + wn*64 + ni*8 + gc;
                float v0 = c[mi][ni][half*2+0];
                float v1 = c[mi][ni][half*2+1];
                if(PHASE==1){
                    const float2 bb = *(const float2*)(b1 + (size_t)blockIdx.z*DIM + col);
                    float o0 = fmaxf(v0 + bb.x, 0.f)*gate;
                    float o1 = fmaxf(v1 + bb.y, 0.f)*gate;
                    *(__half2*)(g_Hh + ((size_t)blockIdx.z*NTOK + row)*DIM + col) =
                        __floats2half2_rn(o0, o1);
                } else {
                    *(float2*)(dout + (size_t)row*DIM + col) = make_float2(v0, v1);
                }
            }
        }
    }
}

// gates blocks in prep_kernel need Wgt first — to avoid intra-launch ordering,
// run the tiny Wg transpose as its own kernel before prep (3 us).
__global__ void wg_transpose_kernel(const float* __restrict__ Wg){
    int j = blockIdx.x*256 + threadIdx.x;   // 4096... only DIM=1024 needed
    if(j < DIM){
        #pragma unroll 1
        for(int s=0; s<NSK; s++)
            g_Wgt[(size_t)s*DIM + j] = Wg[(size_t)j*NSK + s];
    }
}

// ---------------- launch ----------------
extern "C" void kernel_launch(void* const* d_in, const int* in_sizes, int n_in,
                              void* d_out, int out_size){
    const float* x  = (const float*)d_in[0];
    const float* W1 = (const float*)d_in[1];
    const float* b1 = (const float*)d_in[2];
    const float* W2 = (const float*)d_in[3];
    const float* b2 = (const float*)d_in[4];
    const float* Wg = (const float*)d_in[5];
    const float* bg = (const float*)d_in[6];
    float* out = (float*)d_out;

    cudaFuncSetAttribute(gemm_kernel<1>, cudaFuncAttributeMaxDynamicSharedMemorySize, SMEM_DYN);
    cudaFuncSetAttribute(gemm_kernel<2>, cudaFuncAttributeMaxDynamicSharedMemorySize, SMEM_DYN);

    wg_transpose_kernel<<<4, 256>>>(Wg);
    prep_kernel<<<NCONV + NTOK + 2, 256>>>(x, W1, W2, Wg, bg);
    gemm_kernel<1><<<dim3(NTOK/BM, DIM/BN, NSK), 256, SMEM_DYN>>>(b1, nullptr, nullptr);
    gemm_kernel<2><<<dim3(NTOK/BM, DIM/BN), 256, SMEM_DYN>>>(nullptr, b2, out);
}

// round 10
// speedup vs baseline: 1.0872x; 1.0872x over previous
#include <cuda_runtime.h>
#include <cuda_fp16.h>
#include <cstdint>

#define DIM  1024
#define NTOK 4096
#define NSK  50
#define BM 128
#define BN 128
#define BK 64                             // 64 halves (A cols) / 64 k-rows (B)
#define NSTAGE 3
#define A_BYTES (BM*128)                  // 16KB per stage: 128 m-rows x 128B
#define B_BYTES (BK*256)                  // 16KB per stage: 64 k-rows x 256B
#define SMEM_DYN (NSTAGE*(A_BYTES+B_BYTES) + 1024)   // 99328 -> 2 CTAs/SM

// ---------------- scratch (static device, allocation-free) ----------------
__device__ __half g_Xh [(size_t)NTOK*DIM];
__device__ __half g_W1h[(size_t)NSK*DIM*DIM];        // original layout [e][d][h]
__device__ __half g_W2h[(size_t)NSK*DIM*DIM];        // original layout [e][h][d]
__device__ __half g_Hh [(size_t)NSK*NTOK*DIM];       // gate-scaled hidden [e][m][h]
__device__ float  g_gates[(size_t)NTOK*NSK];
__device__ float  g_Wgt[64*DIM];                      // transposed gate weights [s][j]

// ---------------- helpers ----------------
__device__ __forceinline__ uint32_t smem_u32(const void* p){
    uint32_t a; asm("{ .reg .u64 t; cvta.to.shared.u64 t, %1; cvt.u32.u64 %0, t; }":"=r"(a):"l"(p)); return a;
}
__device__ __forceinline__ void cp_async16(uint32_t s, const void* gp){
    uint64_t g = __cvta_generic_to_global(gp);
    asm volatile("cp.async.cg.shared.global [%0], [%1], 16;"::"r"(s),"l"(g));
}
#define CP_COMMIT() asm volatile("cp.async.commit_group;":::"memory")

#define LDSM_X4(r, a) \
    asm volatile("ldmatrix.sync.aligned.m8n8.x4.shared.b16 {%0,%1,%2,%3}, [%4];" \
        : "=r"((r)[0]),"=r"((r)[1]),"=r"((r)[2]),"=r"((r)[3]) : "r"(a))

#define LDSM_X4_T(r, a) \
    asm volatile("ldmatrix.sync.aligned.m8n8.x4.trans.shared.b16 {%0,%1,%2,%3}, [%4];" \
        : "=r"((r)[0]),"=r"((r)[1]),"=r"((r)[2]),"=r"((r)[3]) : "r"(a))

#define MMA_F16(c, a, b0, b1) \
    asm volatile("mma.sync.aligned.m16n8k16.row.col.f32.f16.f16.f32 " \
        "{%0,%1,%2,%3},{%4,%5,%6,%7},{%8,%9},{%0,%1,%2,%3};" \
        : "+f"((c)[0]),"+f"((c)[1]),"+f"((c)[2]),"+f"((c)[3]) \
        : "r"((a)[0]),"r"((a)[1]),"r"((a)[2]),"r"((a)[3]),"r"(b0),"r"(b1))

// ---------------- prep kernels (R8 shape) ----------------
__global__ void wg_transpose_kernel(const float* __restrict__ Wg){
    __shared__ float t[32][33];
    int j0 = blockIdx.x*32, s0 = blockIdx.y*32;
    int tx = threadIdx.x, ty = threadIdx.y;
    #pragma unroll
    for(int r=ty; r<32; r+=8)
        t[r][tx] = (s0+tx < NSK) ? Wg[(size_t)(j0+r)*NSK + s0+tx] : 0.f;
    __syncthreads();
    #pragma unroll
    for(int r=ty; r<32; r+=8)
        if(s0+r < NSK) g_Wgt[(size_t)(s0+r)*DIM + j0+tx] = t[tx][r];
}

__global__ void convert_w_kernel(const float* __restrict__ W1, const float* __restrict__ W2){
    const float* src = blockIdx.y ? W2 : W1;
    __half* dst = blockIdx.y ? g_W2h : g_W1h;
    size_t base = (size_t)blockIdx.x*2048 + (size_t)threadIdx.x*8;
    float4 a = *(const float4*)(src + base);
    float4 b = *(const float4*)(src + base + 4);
    __half2 h[4];
    h[0] = __floats2half2_rn(a.x, a.y); h[1] = __floats2half2_rn(a.z, a.w);
    h[2] = __floats2half2_rn(b.x, b.y); h[3] = __floats2half2_rn(b.z, b.w);
    *(uint4*)(dst + base) = *(uint4*)h;
}

__global__ void gates_kernel(const float* __restrict__ x, const float* __restrict__ bg){
    int n = blockIdx.x, tid = threadIdx.x;
    __shared__ float xs[DIM]; __shared__ float raw[64]; __shared__ float ssum;
    for(int j=tid; j<DIM; j+=128){
        float v = x[(size_t)n*DIM + j];
        xs[j] = v;
        g_Xh[(size_t)n*DIM + j] = __float2half_rn(v);
    }
    __syncthreads();
    int wid = tid>>5, lid = tid&31;
    for(int s=wid; s<NSK; s+=4){
        float acc = 0.f;
        #pragma unroll 8
        for(int j=lid; j<DIM; j+=32) acc += xs[j]*g_Wgt[(size_t)s*DIM + j];
        #pragma unroll
        for(int o=16;o;o>>=1) acc += __shfl_xor_sync(0xFFFFFFFFu, acc, o);
        if(lid==0) raw[s] = acc + bg[s];
    }
    __syncthreads();
    if(tid==0){
        float m = -1e30f;
        for(int s=0;s<NSK;s++) m = fmaxf(m, raw[s]);
        float sm = 0.f;
        for(int s=0;s<NSK;s++){ float e = __expf(raw[s]-m); raw[s]=e; sm+=e; }
        ssum = sm;
    }
    __syncthreads();
    if(tid<NSK) g_gates[(size_t)n*NSK + tid] = raw[tid]/ssum;
}

// ---------------- main fp16 mma.sync GEMM ----------------
// 8 warps, warp grid 2x4, warp tile 64x32, 2 CTAs/SM (latency hiding via TLP).
// PHASE 1: Hh[e][m][h] = half( gates[m][e]*relu( Xh @ W1[e] + b1[e] ) )  grid (32,8,50)
// PHASE 2: out[m][d] = sum_e g*b2 (prologue) + Hh_all @ W2_all (K=51200)  grid (32,8)
template<int PHASE>
__global__ void __launch_bounds__(256,2) gemm_kernel(const float* __restrict__ b1,
                                                     const float* __restrict__ b2,
                                                     float* __restrict__ dout){
    extern __shared__ char dsm[];
    const uint32_t sb = (smem_u32(dsm) + 1023u) & ~1023u;
    const uint32_t A0 = sb, B0 = sb + NSTAGE*A_BYTES;
    const int tid = threadIdx.x, wid = tid>>5, lane = tid&31;
    const int wm = wid & 1, wn = wid >> 1;            // 2x4 warp grid
    const int m0 = blockIdx.x*BM, n0 = blockIdx.y*BN;
    const int NS = (PHASE==1) ? (DIM/BK) : (NSK*DIM/BK);   // 16 / 800

    const int mat = lane>>3, rr = lane&7;
    const int a_rowl = (mat&1)*8 + rr;
    const int a_bc   = (mat>>1)*16;
    const uint32_t xorv = (uint32_t)(rr<<4);
    const int b_row  = lane & 15;
    const int b_noff = (lane >> 4) * 16;
    const int gr = lane>>2, gc = (lane&3)*2;

    float c[4][4][4];
    #pragma unroll
    for(int i=0;i<4;i++)
      #pragma unroll
      for(int j=0;j<4;j++)
        #pragma unroll
        for(int k=0;k<4;k++) c[i][j][k] = 0.f;

    auto load_tile = [&](int step){
        const __half *Ag, *Bg;
        if(PHASE==1){
            int e = blockIdx.z, kk = step*BK;
            Ag = g_Xh  + (size_t)m0*DIM + kk;
            Bg = g_W1h + (size_t)e*DIM*DIM + (size_t)kk*DIM + n0;
        } else {
            int e = step>>4, kk = (step&15)*BK;
            Ag = g_Hh  + ((size_t)e*NTOK + m0)*DIM + kk;
            Bg = g_W2h + (size_t)e*DIM*DIM + (size_t)kk*DIM + n0;
        }
        int stg = step % NSTAGE;
        uint32_t as = A0 + stg*A_BYTES, bs = B0 + stg*B_BYTES;
        #pragma unroll
        for(int i=0;i<4;i++){ int q = tid + i*256; int r=q>>3, cc=q&7;
            cp_async16(as + (uint32_t)(r*128 + ((cc*16) ^ ((r&7)<<4))), Ag + (size_t)r*DIM + cc*8); }
        #pragma unroll
        for(int i=0;i<4;i++){ int q = tid + i*256; int r=q>>4, cc=q&15;
            cp_async16(bs + (uint32_t)(r*256 + ((cc*16) ^ ((r&7)<<4))), Bg + (size_t)r*DIM + cc*8); }
        CP_COMMIT();
    };

    load_tile(0); load_tile(1);

    // PHASE 2 prologue (overlapped with pipeline fill): c = sum_e gates*b2
    if(PHASE==2){
        for(int e=0; e<NSK; e++){
            float gg[4][2];
            #pragma unroll
            for(int mi=0; mi<4; mi++)
                #pragma unroll
                for(int half=0; half<2; half++)
                    gg[mi][half] = g_gates[(size_t)(m0 + wm*64 + mi*16 + gr + half*8)*NSK + e];
            #pragma unroll
            for(int ni=0; ni<4; ni++){
                const float2 bb = *(const float2*)(b2 + (size_t)e*DIM + n0 + wn*32 + ni*8 + gc);
                #pragma unroll
                for(int mi=0; mi<4; mi++)
                    #pragma unroll
                    for(int half=0; half<2; half++){
                        c[mi][ni][half*2+0] += gg[mi][half]*bb.x;
                        c[mi][ni][half*2+1] += gg[mi][half]*bb.y;
                    }
            }
        }
    }

    for(int step=0; step<NS; step++){
        if(step < NS-1) asm volatile("cp.async.wait_group 1;":::"memory");
        else            asm volatile("cp.async.wait_group 0;":::"memory");
        __syncthreads();
        if(step+2 < NS) load_tile(step+2);

        int stg = step % NSTAGE;
        const uint32_t as = A0 + stg*A_BYTES;
        const uint32_t bs = B0 + stg*B_BYTES;
        #pragma unroll
        for(int ks=0; ks<4; ks++){      // 4 k16 slices per BK=64
            uint32_t a[4][4], b[2][4];
            #pragma unroll
            for(int mi=0; mi<4; mi++){
                int row = wm*64 + mi*16 + a_rowl;
                LDSM_X4(a[mi], as + (uint32_t)(row*128) + (((uint32_t)(ks*32 + a_bc)) ^ xorv));
            }
            #pragma unroll
            for(int p=0; p<2; p++){
                int rowk = ks*16 + b_row;
                uint32_t bcol = (uint32_t)(wn*64 + p*32 + b_noff);
                LDSM_X4_T(b[p], bs + (uint32_t)(rowk*256) + (bcol ^ (uint32_t)((rowk&7)<<4)));
            }
            #pragma unroll
            for(int mi=0; mi<4; mi++)
                #pragma unroll
                for(int ni=0; ni<4; ni++)
                    MMA_F16(c[mi][ni], a[mi], b[ni>>1][(ni&1)*2], b[ni>>1][(ni&1)*2+1]);
        }
        __syncthreads();
    }

    // ---------------- epilogue ----------------
    #pragma unroll
    for(int mi=0; mi<4; mi++){
        int r0 = m0 + wm*64 + mi*16 + gr;
        #pragma unroll
        for(int half=0; half<2; half++){
            int row = r0 + half*8;
            float gate = 0.f;
            if(PHASE==1) gate = g_gates[(size_t)row*NSK + blockIdx.z];
            #pragma unroll
            for(int ni=0; ni<4; ni++){
                int col = n0 + wn*32 + ni*8 + gc;
                float v0 = c[mi][ni][half*2+0];
                float v1 = c[mi][ni][half*2+1];
                if(PHASE==1){
                    const float2 bb = *(const float2*)(b1 + (size_t)blockIdx.z*DIM + col);
                    float o0 = fmaxf(v0 + bb.x, 0.f)*gate;
                    float o1 = fmaxf(v1 + bb.y, 0.f)*gate;
                    *(__half2*)(g_Hh + ((size_t)blockIdx.z*NTOK + row)*DIM + col) =
                        __floats2half2_rn(o0, o1);
                } else {
                    *(float2*)(dout + (size_t)row*DIM + col) = make_float2(v0, v1);
                }
            }
        }
    }
}

// ---------------- launch ----------------
extern "C" void kernel_launch(void* const* d_in, const int* in_sizes, int n_in,
                              void* d_out, int out_size){
    const float* x  = (const float*)d_in[0];
    const float* W1 = (const float*)d_in[1];
    const float* b1 = (const float*)d_in[2];
    const float* W2 = (const float*)d_in[3];
    const float* b2 = (const float*)d_in[4];
    const float* Wg = (const float*)d_in[5];
    const float* bg = (const float*)d_in[6];
    float* out = (float*)d_out;

    cudaFuncSetAttribute(gemm_kernel<1>, cudaFuncAttributeMaxDynamicSharedMemorySize, SMEM_DYN);
    cudaFuncSetAttribute(gemm_kernel<2>, cudaFuncAttributeMaxDynamicSharedMemorySize, SMEM_DYN);

    wg_transpose_kernel<<<dim3(32, 2), dim3(32, 8)>>>(Wg);
    gates_kernel<<<NTOK, 128>>>(x, bg);
    convert_w_kernel<<<dim3(25600, 2), 256>>>(W1, W2);
    gemm_kernel<1><<<dim3(NTOK/BM, DIM/BN, NSK), 256, SMEM_DYN>>>(b1, nullptr, nullptr);
    gemm_kernel<2><<<dim3(NTOK/BM, DIM/BN), 256, SMEM_DYN>>>(nullptr, b2, out);
}

// round 11
// speedup vs baseline: 1.0883x; 1.0010x over previous
#include <cuda_runtime.h>
#include <cuda_fp16.h>
#include <cstdint>

#define DIM  1024
#define NTOK 4096
#define NSK  50
#define BM 128
#define BN 128
#define BK 64
#define NSTAGE 3
#define A_BYTES (BM*128)                  // 16KB per stage
#define B_BYTES (BK*256)                  // 16KB per stage
#define SMEM_DYN (NSTAGE*(A_BYTES+B_BYTES) + 1024)   // 99328 -> 2 CTAs/SM

// epilogue staging: 128 rows x 272B pitch (136 halves) = 34.8KB (fits in stages)
#define EPIT 136

// ---------------- scratch ----------------
__device__ __half g_Xh [(size_t)NTOK*DIM];
__device__ __half g_W1h[(size_t)NSK*DIM*DIM];        // [e][d][h]
__device__ __half g_W2h[(size_t)NSK*DIM*DIM];        // [e][h][d]
__device__ __half g_Hh [(size_t)NSK*NTOK*DIM];       // [e][m][h]
__device__ float  g_gates[(size_t)NTOK*NSK];
__device__ float  g_Wgt[64*DIM];

// ---------------- helpers ----------------
__device__ __forceinline__ uint32_t smem_u32(const void* p){
    uint32_t a; asm("{ .reg .u64 t; cvta.to.shared.u64 t, %1; cvt.u32.u64 %0, t; }":"=r"(a):"l"(p)); return a;
}
__device__ __forceinline__ void cp_async16(uint32_t s, const void* gp){
    uint64_t g = __cvta_generic_to_global(gp);
    asm volatile("cp.async.cg.shared.global [%0], [%1], 16;"::"r"(s),"l"(g));
}
#define CP_COMMIT() asm volatile("cp.async.commit_group;":::"memory")

#define LDSM_X4(r, a) \
    asm volatile("ldmatrix.sync.aligned.m8n8.x4.shared.b16 {%0,%1,%2,%3}, [%4];" \
        : "=r"((r)[0]),"=r"((r)[1]),"=r"((r)[2]),"=r"((r)[3]) : "r"(a))

#define LDSM_X4_T(r, a) \
    asm volatile("ldmatrix.sync.aligned.m8n8.x4.trans.shared.b16 {%0,%1,%2,%3}, [%4];" \
        : "=r"((r)[0]),"=r"((r)[1]),"=r"((r)[2]),"=r"((r)[3]) : "r"(a))

#define MMA_F16(c, a, b0, b1) \
    asm volatile("mma.sync.aligned.m16n8k16.row.col.f32.f16.f16.f32 " \
        "{%0,%1,%2,%3},{%4,%5,%6,%7},{%8,%9},{%0,%1,%2,%3};" \
        : "+f"((c)[0]),"+f"((c)[1]),"+f"((c)[2]),"+f"((c)[3]) \
        : "r"((a)[0]),"r"((a)[1]),"r"((a)[2]),"r"((a)[3]),"r"(b0),"r"(b1))

// ---------------- prep kernels ----------------
__global__ void wg_transpose_kernel(const float* __restrict__ Wg){
    __shared__ float t[32][33];
    int j0 = blockIdx.x*32, s0 = blockIdx.y*32;
    int tx = threadIdx.x, ty = threadIdx.y;
    #pragma unroll
    for(int r=ty; r<32; r+=8)
        t[r][tx] = (s0+tx < NSK) ? Wg[(size_t)(j0+r)*NSK + s0+tx] : 0.f;
    __syncthreads();
    #pragma unroll
    for(int r=ty; r<32; r+=8)
        if(s0+r < NSK) g_Wgt[(size_t)(s0+r)*DIM + j0+tx] = t[tx][r];
}

__global__ void convert_w_kernel(const float* __restrict__ W1, const float* __restrict__ W2){
    const float* src = blockIdx.y ? W2 : W1;
    __half* dst = blockIdx.y ? g_W2h : g_W1h;
    size_t base = (size_t)blockIdx.x*2048 + (size_t)threadIdx.x*8;
    float4 a = *(const float4*)(src + base);
    float4 b = *(const float4*)(src + base + 4);
    __half2 h[4];
    h[0] = __floats2half2_rn(a.x, a.y); h[1] = __floats2half2_rn(a.z, a.w);
    h[2] = __floats2half2_rn(b.x, b.y); h[3] = __floats2half2_rn(b.z, b.w);
    *(uint4*)(dst + base) = *(uint4*)h;
}

__global__ void gates_kernel(const float* __restrict__ x, const float* __restrict__ bg){
    int n = blockIdx.x, tid = threadIdx.x;   // 256 threads
    __shared__ float xs[DIM]; __shared__ float raw[64]; __shared__ float ssum;
    for(int j=tid; j<DIM; j+=256){
        float v = x[(size_t)n*DIM + j];
        xs[j] = v;
        g_Xh[(size_t)n*DIM + j] = __float2half_rn(v);
    }
    __syncthreads();
    int wid = tid>>5, lid = tid&31;
    for(int s=wid; s<NSK; s+=8){
        float acc = 0.f;
        #pragma unroll 8
        for(int j=lid; j<DIM; j+=32) acc += xs[j]*g_Wgt[(size_t)s*DIM + j];
        #pragma unroll
        for(int o=16;o;o>>=1) acc += __shfl_xor_sync(0xFFFFFFFFu, acc, o);
        if(lid==0) raw[s] = acc + bg[s];
    }
    __syncthreads();
    if(tid==0){
        float m = -1e30f;
        for(int s=0;s<NSK;s++) m = fmaxf(m, raw[s]);
        float sm = 0.f;
        for(int s=0;s<NSK;s++){ float e = __expf(raw[s]-m); raw[s]=e; sm+=e; }
        ssum = sm;
    }
    __syncthreads();
    if(tid<NSK) g_gates[(size_t)n*NSK + tid] = raw[tid]/ssum;
}

// ---------------- main fp16 mma.sync GEMM ----------------
// 8 warps, warp grid 2x4, warp tile 64x32, 2 CTAs/SM.
template<int PHASE>
__global__ void __launch_bounds__(256,2) gemm_kernel(const float* __restrict__ b1,
                                                     const float* __restrict__ b2,
                                                     float* __restrict__ dout){
    extern __shared__ char dsm[];
    const uint32_t sb = (smem_u32(dsm) + 1023u) & ~1023u;
    const uint32_t A0 = sb, B0 = sb + NSTAGE*A_BYTES;
    const int tid = threadIdx.x, wid = tid>>5, lane = tid&31;
    const int wm = wid & 1, wn = wid >> 1;
    const int m0 = blockIdx.x*BM, n0 = blockIdx.y*BN;
    const int NS = (PHASE==1) ? (DIM/BK) : (NSK*DIM/BK);   // 16 / 800

    const int mat = lane>>3, rr = lane&7;
    const int a_rowl = (mat&1)*8 + rr;
    const int a_bc   = (mat>>1)*16;
    const uint32_t xorv = (uint32_t)(rr<<4);
    const int b_row  = lane & 15;
    const int b_noff = (lane >> 4) * 16;
    const int gr = lane>>2, gc = (lane&3)*2;

    float c[4][4][4];
    #pragma unroll
    for(int i=0;i<4;i++)
      #pragma unroll
      for(int j=0;j<4;j++)
        #pragma unroll
        for(int k=0;k<4;k++) c[i][j][k] = 0.f;

    auto load_tile = [&](int step){
        const __half *Ag, *Bg;
        if(PHASE==1){
            int e = blockIdx.z, kk = step*BK;
            Ag = g_Xh  + (size_t)m0*DIM + kk;
            Bg = g_W1h + (size_t)e*DIM*DIM + (size_t)kk*DIM + n0;
        } else {
            int e = step>>4, kk = (step&15)*BK;
            Ag = g_Hh  + ((size_t)e*NTOK + m0)*DIM + kk;
            Bg = g_W2h + (size_t)e*DIM*DIM + (size_t)kk*DIM + n0;
        }
        int stg = step % NSTAGE;
        uint32_t as = A0 + stg*A_BYTES, bs = B0 + stg*B_BYTES;
        #pragma unroll
        for(int i=0;i<4;i++){ int q = tid + i*256; int r=q>>3, cc=q&7;
            cp_async16(as + (uint32_t)(r*128 + ((cc*16) ^ ((r&7)<<4))), Ag + (size_t)r*DIM + cc*8); }
        #pragma unroll
        for(int i=0;i<4;i++){ int q = tid + i*256; int r=q>>4, cc=q&15;
            cp_async16(bs + (uint32_t)(r*256 + ((cc*16) ^ ((r&7)<<4))), Bg + (size_t)r*DIM + cc*8); }
        CP_COMMIT();
    };

    load_tile(0); load_tile(1);

    if(PHASE==2){
        for(int e=0; e<NSK; e++){
            float gg[4][2];
            #pragma unroll
            for(int mi=0; mi<4; mi++)
                #pragma unroll
                for(int half=0; half<2; half++)
                    gg[mi][half] = g_gates[(size_t)(m0 + wm*64 + mi*16 + gr + half*8)*NSK + e];
            #pragma unroll
            for(int ni=0; ni<4; ni++){
                const float2 bb = *(const float2*)(b2 + (size_t)e*DIM + n0 + wn*32 + ni*8 + gc);
                #pragma unroll
                for(int mi=0; mi<4; mi++)
                    #pragma unroll
                    for(int half=0; half<2; half++){
                        c[mi][ni][half*2+0] += gg[mi][half]*bb.x;
                        c[mi][ni][half*2+1] += gg[mi][half]*bb.y;
                    }
            }
        }
    }

    for(int step=0; step<NS; step++){
        if(step < NS-1) asm volatile("cp.async.wait_group 1;":::"memory");
        else            asm volatile("cp.async.wait_group 0;":::"memory");
        __syncthreads();                    // single barrier per step
        if(step+2 < NS) load_tile(step+2);

        int stg = step % NSTAGE;
        const uint32_t as = A0 + stg*A_BYTES;
        const uint32_t bs = B0 + stg*B_BYTES;
        #pragma unroll
        for(int ks=0; ks<4; ks++){
            uint32_t a[4][4], b[2][4];
            #pragma unroll
            for(int mi=0; mi<4; mi++){
                int row = wm*64 + mi*16 + a_rowl;
                LDSM_X4(a[mi], as + (uint32_t)(row*128) + (((uint32_t)(ks*32 + a_bc)) ^ xorv));
            }
            #pragma unroll
            for(int p=0; p<2; p++){
                int rowk = ks*16 + b_row;
                uint32_t bcol = (uint32_t)(wn*64 + p*32 + b_noff);
                LDSM_X4_T(b[p], bs + (uint32_t)(rowk*256) + (bcol ^ (uint32_t)((rowk&7)<<4)));
            }
            #pragma unroll
            for(int mi=0; mi<4; mi++)
                #pragma unroll
                for(int ni=0; ni<4; ni++)
                    MMA_F16(c[mi][ni], a[mi], b[ni>>1][(ni&1)*2], b[ni>>1][(ni&1)*2+1]);
        }
    }
    __syncthreads();   // all compute done before smem reuse / epilogue

    if(PHASE==1){
        // stage fp16 results in smem (pitch EPIT halves = 272B), then coalesced STG
        __half* hs = (__half*)(dsm + (sb - smem_u32(dsm)));
        int e = blockIdx.z;
        #pragma unroll
        for(int mi=0; mi<4; mi++){
            #pragma unroll
            for(int half=0; half<2; half++){
                int row = wm*64 + mi*16 + gr + half*8;
                float gate = g_gates[(size_t)(m0+row)*NSK + e];
                #pragma unroll
                for(int ni=0; ni<4; ni++){
                    int col = wn*32 + ni*8 + gc;
                    const float2 bb = *(const float2*)(b1 + (size_t)e*DIM + n0 + col);
                    float o0 = fmaxf(c[mi][ni][half*2+0] + bb.x, 0.f)*gate;
                    float o1 = fmaxf(c[mi][ni][half*2+1] + bb.y, 0.f)*gate;
                    *(__half2*)(hs + (size_t)row*EPIT + col) = __floats2half2_rn(o0, o1);
                }
            }
        }
        __syncthreads();
        // 128 rows x 256B, 16 threads x 16B per row, 8 passes
        #pragma unroll
        for(int pass=0; pass<8; pass++){
            int q = tid + pass*256;
            int row = q >> 4, ch = q & 15;
            uint4 v = *(const uint4*)(hs + (size_t)row*EPIT + ch*8);
            *(uint4*)(g_Hh + ((size_t)e*NTOK + m0 + row)*DIM + n0 + ch*8) = v;
        }
    } else {
        #pragma unroll
        for(int mi=0; mi<4; mi++){
            int r0 = m0 + wm*64 + mi*16 + gr;
            #pragma unroll
            for(int half=0; half<2; half++){
                int row = r0 + half*8;
                #pragma unroll
                for(int ni=0; ni<4; ni++){
                    int col = n0 + wn*32 + ni*8 + gc;
                    *(float2*)(dout + (size_t)row*DIM + col) =
                        make_float2(c[mi][ni][half*2+0], c[mi][ni][half*2+1]);
                }
            }
        }
    }
}

// ---------------- launch ----------------
extern "C" void kernel_launch(void* const* d_in, const int* in_sizes, int n_in,
                              void* d_out, int out_size){
    const float* x  = (const float*)d_in[0];
    const float* W1 = (const float*)d_in[1];
    const float* b1 = (const float*)d_in[2];
    const float* W2 = (const float*)d_in[3];
    const float* b2 = (const float*)d_in[4];
    const float* Wg = (const float*)d_in[5];
    const float* bg = (const float*)d_in[6];
    float* out = (float*)d_out;

    cudaFuncSetAttribute(gemm_kernel<1>, cudaFuncAttributeMaxDynamicSharedMemorySize, SMEM_DYN);
    cudaFuncSetAttribute(gemm_kernel<2>, cudaFuncAttributeMaxDynamicSharedMemorySize, SMEM_DYN);

    wg_transpose_kernel<<<dim3(32, 2), dim3(32, 8)>>>(Wg);
    gates_kernel<<<NTOK, 256>>>(x, bg);
    convert_w_kernel<<<dim3(25600, 2), 256>>>(W1, W2);
    gemm_kernel<1><<<dim3(NTOK/BM, DIM/BN, NSK), 256, SMEM_DYN>>>(b1, nullptr, nullptr);
    gemm_kernel<2><<<dim3(NTOK/BM, DIM/BN), 256, SMEM_DYN>>>(nullptr, b2, out);
}

// round 13
// speedup vs baseline: 1.0906x; 1.0022x over previous
#include <cuda_runtime.h>
#include <cuda_fp16.h>
#include <cstdint>

#define DIM  1024
#define NTOK 4096
#define NSK  50
#define BM 128
#define BN 128
#define BK 64
#define NSTAGE 3
#define A_BYTES (BM*128)                  // 16KB per stage
#define B_BYTES (BK*256)                  // 16KB per stage
#define SMEM_DYN (NSTAGE*(A_BYTES+B_BYTES) + 1024)   // 99328 -> 2 CTAs/SM
#define EPIT 136                          // epilogue staging pitch (halves)

// ---------------- scratch ----------------
__device__ __half g_Xh [(size_t)NTOK*DIM];
__device__ __half g_W1h[(size_t)NSK*DIM*DIM];        // [e][d][h]
__device__ __half g_W2h[(size_t)NSK*DIM*DIM];        // [e][h][d]
__device__ __half g_Hh [(size_t)NSK*NTOK*DIM];       // [e][m][h]
__device__ float  g_gates[(size_t)NTOK*NSK];
__device__ float  g_Wgt[64*DIM];

// ---------------- helpers ----------------
__device__ __forceinline__ uint32_t smem_u32(const void* p){
    uint32_t a; asm("{ .reg .u64 t; cvta.to.shared.u64 t, %1; cvt.u32.u64 %0, t; }":"=r"(a):"l"(p)); return a;
}
__device__ __forceinline__ void cp_async16(uint32_t s, const void* gp){
    uint64_t g = __cvta_generic_to_global(gp);
    asm volatile("cp.async.cg.shared.global [%0], [%1], 16;"::"r"(s),"l"(g));
}
#define CP_COMMIT() asm volatile("cp.async.commit_group;":::"memory")

#define LDSM_X4(r, a) \
    asm volatile("ldmatrix.sync.aligned.m8n8.x4.shared.b16 {%0,%1,%2,%3}, [%4];" \
        : "=r"((r)[0]),"=r"((r)[1]),"=r"((r)[2]),"=r"((r)[3]) : "r"(a))

#define LDSM_X4_T(r, a) \
    asm volatile("ldmatrix.sync.aligned.m8n8.x4.trans.shared.b16 {%0,%1,%2,%3}, [%4];" \
        : "=r"((r)[0]),"=r"((r)[1]),"=r"((r)[2]),"=r"((r)[3]) : "r"(a))

#define MMA_F16(c, a, b0, b1) \
    asm volatile("mma.sync.aligned.m16n8k16.row.col.f32.f16.f16.f32 " \
        "{%0,%1,%2,%3},{%4,%5,%6,%7},{%8,%9},{%0,%1,%2,%3};" \
        : "+f"((c)[0]),"+f"((c)[1]),"+f"((c)[2]),"+f"((c)[3]) \
        : "r"((a)[0]),"r"((a)[1]),"r"((a)[2]),"r"((a)[3]),"r"(b0),"r"(b1))

// ---------------- prep kernels ----------------
__global__ void wg_transpose_kernel(const float* __restrict__ Wg){
    __shared__ float t[32][33];
    int j0 = blockIdx.x*32, s0 = blockIdx.y*32;
    int tx = threadIdx.x, ty = threadIdx.y;
    #pragma unroll
    for(int r=ty; r<32; r+=8)
        t[r][tx] = (s0+tx < NSK) ? Wg[(size_t)(j0+r)*NSK + s0+tx] : 0.f;
    __syncthreads();
    #pragma unroll
    for(int r=ty; r<32; r+=8)
        if(s0+r < NSK) g_Wgt[(size_t)(s0+r)*DIM + j0+tx] = t[tx][r];
}

__global__ void convert_w_kernel(const float* __restrict__ W1, const float* __restrict__ W2){
    const float* src = blockIdx.y ? W2 : W1;
    __half* dst = blockIdx.y ? g_W2h : g_W1h;
    size_t base = (size_t)blockIdx.x*2048 + (size_t)threadIdx.x*8;
    float4 a = *(const float4*)(src + base);
    float4 b = *(const float4*)(src + base + 4);
    __half2 h[4];
    h[0] = __floats2half2_rn(a.x, a.y); h[1] = __floats2half2_rn(a.z, a.w);
    h[2] = __floats2half2_rn(b.x, b.y); h[3] = __floats2half2_rn(b.z, b.w);
    *(uint4*)(dst + base) = *(uint4*)h;
}

__global__ void gates_kernel(const float* __restrict__ x, const float* __restrict__ bg){
    int n = blockIdx.x, tid = threadIdx.x;   // 256 threads
    __shared__ float xs[DIM]; __shared__ float raw[64]; __shared__ float ssum;
    for(int j=tid; j<DIM; j+=256){
        float v = x[(size_t)n*DIM + j];
        xs[j] = v;
        g_Xh[(size_t)n*DIM + j] = __float2half_rn(v);
    }
    __syncthreads();
    int wid = tid>>5, lid = tid&31;
    for(int s=wid; s<NSK; s+=8){
        float acc = 0.f;
        #pragma unroll 8
        for(int j=lid; j<DIM; j+=32) acc += xs[j]*g_Wgt[(size_t)s*DIM + j];
        #pragma unroll
        for(int o=16;o;o>>=1) acc += __shfl_xor_sync(0xFFFFFFFFu, acc, o);
        if(lid==0) raw[s] = acc + bg[s];
    }
    __syncthreads();
    if(tid==0){
        float m = -1e30f;
        for(int s=0;s<NSK;s++) m = fmaxf(m, raw[s]);
        float sm = 0.f;
        for(int s=0;s<NSK;s++){ float e = __expf(raw[s]-m); raw[s]=e; sm+=e; }
        ssum = sm;
    }
    __syncthreads();
    if(tid<NSK) g_gates[(size_t)n*NSK + tid] = raw[tid]/ssum;
}

// ---------------- main fp16 mma.sync GEMM ----------------
// 4 warps (128 thr), warp grid 2x2, warp tile 64x64, 2 CTAs/SM.
// Crossbar cost: 1.5 wavefronts/MMA (was 2.0) -> tensor pipe is sole binder.
template<int PHASE>
__global__ void __launch_bounds__(128,2) gemm_kernel(const float* __restrict__ b1,
                                                     const float* __restrict__ b2,
                                                     float* __restrict__ dout){
    extern __shared__ char dsm[];
    const uint32_t sb = (smem_u32(dsm) + 1023u) & ~1023u;
    const uint32_t A0 = sb, B0 = sb + NSTAGE*A_BYTES;
    const int tid = threadIdx.x, wid = tid>>5, lane = tid&31;
    const int wm = wid & 1, wn = wid >> 1;            // 2x2 warp grid
    const int m0 = blockIdx.x*BM, n0 = blockIdx.y*BN;
    const int NS = (PHASE==1) ? (DIM/BK) : (NSK*DIM/BK);   // 16 / 800

    const int mat = lane>>3, rr = lane&7;
    const int a_rowl = (mat&1)*8 + rr;
    const int a_bc   = (mat>>1)*16;
    const uint32_t xorv = (uint32_t)(rr<<4);
    const int b_row  = lane & 15;
    const int b_noff = (lane >> 4) * 16;
    const int gr = lane>>2, gc = (lane&3)*2;

    float c[4][8][4];
    #pragma unroll
    for(int i=0;i<4;i++)
      #pragma unroll
      for(int j=0;j<8;j++)
        #pragma unroll
        for(int k=0;k<4;k++) c[i][j][k] = 0.f;

    auto load_tile = [&](int step){
        const __half *Ag, *Bg;
        if(PHASE==1){
            int e = blockIdx.z, kk = step*BK;
            Ag = g_Xh  + (size_t)m0*DIM + kk;
            Bg = g_W1h + (size_t)e*DIM*DIM + (size_t)kk*DIM + n0;
        } else {
            int e = step>>4, kk = (step&15)*BK;
            Ag = g_Hh  + ((size_t)e*NTOK + m0)*DIM + kk;
            Bg = g_W2h + (size_t)e*DIM*DIM + (size_t)kk*DIM + n0;
        }
        int stg = step % NSTAGE;
        uint32_t as = A0 + stg*A_BYTES, bs = B0 + stg*B_BYTES;
        #pragma unroll
        for(int i=0;i<8;i++){ int q = tid + i*128; int r=q>>3, cc=q&7;
            cp_async16(as + (uint32_t)(r*128 + ((cc*16) ^ ((r&7)<<4))), Ag + (size_t)r*DIM + cc*8); }
        #pragma unroll
        for(int i=0;i<8;i++){ int q = tid + i*128; int r=q>>4, cc=q&15;
            cp_async16(bs + (uint32_t)(r*256 + ((cc*16) ^ ((r&7)<<4))), Bg + (size_t)r*DIM + cc*8); }
        CP_COMMIT();
    };

    load_tile(0); load_tile(1);

    // PHASE 2 prologue (overlapped with fill): c = sum_e gates*b2
    if(PHASE==2){
        for(int e=0; e<NSK; e++){
            float gg[4][2];
            #pragma unroll
            for(int mi=0; mi<4; mi++)
                #pragma unroll
                for(int half=0; half<2; half++)
                    gg[mi][half] = g_gates[(size_t)(m0 + wm*64 + mi*16 + gr + half*8)*NSK + e];
            #pragma unroll
            for(int ni=0; ni<8; ni++){
                const float2 bb = *(const float2*)(b2 + (size_t)e*DIM + n0 + wn*64 + ni*8 + gc);
                #pragma unroll
                for(int mi=0; mi<4; mi++)
                    #pragma unroll
                    for(int half=0; half<2; half++){
                        c[mi][ni][half*2+0] += gg[mi][half]*bb.x;
                        c[mi][ni][half*2+1] += gg[mi][half]*bb.y;
                    }
            }
        }
    }

    for(int step=0; step<NS; step++){
        if(step < NS-1) asm volatile("cp.async.wait_group 1;":::"memory");
        else            asm volatile("cp.async.wait_group 0;":::"memory");
        __syncthreads();
        if(step+2 < NS) load_tile(step+2);

        int stg = step % NSTAGE;
        const uint32_t as = A0 + stg*A_BYTES;
        const uint32_t bs = B0 + stg*B_BYTES;
        #pragma unroll
        for(int ks=0; ks<4; ks++){
            uint32_t a[4][4], b[4][4];
            #pragma unroll
            for(int mi=0; mi<4; mi++){
                int row = wm*64 + mi*16 + a_rowl;
                LDSM_X4(a[mi], as + (uint32_t)(row*128) + (((uint32_t)(ks*32 + a_bc)) ^ xorv));
            }
            #pragma unroll
            for(int p=0; p<4; p++){
                int rowk = ks*16 + b_row;
                uint32_t bcol = (uint32_t)(wn*128 + p*32 + b_noff);
                LDSM_X4_T(b[p], bs + (uint32_t)(rowk*256) + (bcol ^ (uint32_t)((rowk&7)<<4)));
            }
            #pragma unroll
            for(int mi=0; mi<4; mi++)
                #pragma unroll
                for(int ni=0; ni<8; ni++)
                    MMA_F16(c[mi][ni], a[mi], b[ni>>1][(ni&1)*2], b[ni>>1][(ni&1)*2+1]);
        }
    }
    __syncthreads();

    if(PHASE==1){
        __half* hs = (__half*)(dsm + (sb - smem_u32(dsm)));
        int e = blockIdx.z;
        #pragma unroll
        for(int mi=0; mi<4; mi++){
            #pragma unroll
            for(int half=0; half<2; half++){
                int row = wm*64 + mi*16 + gr + half*8;
                float gate = g_gates[(size_t)(m0+row)*NSK + e];
                #pragma unroll
                for(int ni=0; ni<8; ni++){
                    int col = wn*64 + ni*8 + gc;
                    const float2 bb = *(const float2*)(b1 + (size_t)e*DIM + n0 + col);
                    float o0 = fmaxf(c[mi][ni][half*2+0] + bb.x, 0.f)*gate;
                    float o1 = fmaxf(c[mi][ni][half*2+1] + bb.y, 0.f)*gate;
                    *(__half2*)(hs + (size_t)row*EPIT + col) = __floats2half2_rn(o0, o1);
                }
            }
        }
        __syncthreads();
        // 128 rows x 256B out, 16 threads x 16B per row, 16 passes of 128 thr
        #pragma unroll
        for(int pass=0; pass<16; pass++){
            int q = tid + pass*128;
            int row = q >> 4, ch = q & 15;
            uint4 v = *(const uint4*)(hs + (size_t)row*EPIT + ch*8);
            *(uint4*)(g_Hh + ((size_t)e*NTOK + m0 + row)*DIM + n0 + ch*8) = v;
        }
    } else {
        #pragma unroll
        for(int mi=0; mi<4; mi++){
            int r0 = m0 + wm*64 + mi*16 + gr;
            #pragma unroll
            for(int half=0; half<2; half++){
                int row = r0 + half*8;
                #pragma unroll
                for(int ni=0; ni<8; ni++){
                    int col = n0 + wn*64 + ni*8 + gc;
                    *(float2*)(dout + (size_t)row*DIM + col) =
                        make_float2(c[mi][ni][half*2+0], c[mi][ni][half*2+1]);
                }
            }
        }
    }
}

// ---------------- launch ----------------
extern "C" void kernel_launch(void* const* d_in, const int* in_sizes, int n_in,
                              void* d_out, int out_size){
    const float* x  = (const float*)d_in[0];
    const float* W1 = (const float*)d_in[1];
    const float* b1 = (const float*)d_in[2];
    const float* W2 = (const float*)d_in[3];
    const float* b2 = (const float*)d_in[4];
    const float* Wg = (const float*)d_in[5];
    const float* bg = (const float*)d_in[6];
    float* out = (float*)d_out;

    cudaFuncSetAttribute(gemm_kernel<1>, cudaFuncAttributeMaxDynamicSharedMemorySize, SMEM_DYN);
    cudaFuncSetAttribute(gemm_kernel<2>, cudaFuncAttributeMaxDynamicSharedMemorySize, SMEM_DYN);

    wg_transpose_kernel<<<dim3(32, 2), dim3(32, 8)>>>(Wg);
    gates_kernel<<<NTOK, 256>>>(x, bg);
    convert_w_kernel<<<dim3(25600, 2), 256>>>(W1, W2);
    gemm_kernel<1><<<dim3(NTOK/BM, DIM/BN, NSK), 128, SMEM_DYN>>>(b1, nullptr, nullptr);
    gemm_kernel<2><<<dim3(NTOK/BM, DIM/BN), 128, SMEM_DYN>>>(nullptr, b2, out);
}

// round 15
// speedup vs baseline: 1.1674x; 1.0705x over previous
#include <cuda_runtime.h>
#include <cuda_fp16.h>
#include <cstdint>

#define DIM  1024
#define NTOK 4096
#define NSK  50
#define BM 128
#define BN 128
#define BK 64
#define NSTAGE 3
#define NSPLIT 4                          // phase-2 K splits
#define A_BYTES (BM*128)                  // 16KB per stage
#define B_BYTES (BK*256)                  // 16KB per stage
#define SMEM_DYN (NSTAGE*(A_BYTES+B_BYTES) + 1024)   // 99328 -> 2 CTAs/SM
#define EPIT 136                          // epilogue staging pitch (halves)

// ---------------- scratch ----------------
__device__ __half g_Xh [(size_t)NTOK*DIM];
__device__ __half g_W1h[(size_t)NSK*DIM*DIM];        // [e][d][h]
__device__ __half g_W2h[(size_t)NSK*DIM*DIM];        // [e][h][d]
__device__ __half g_Hh [(size_t)NSK*NTOK*DIM];       // [e][m][h]
__device__ float  g_gates[(size_t)NTOK*NSK];
__device__ float  g_Wgt[64*DIM];
__device__ float  g_part[(size_t)NSPLIT*NTOK*DIM];   // phase-2 split-K partials

// ---------------- helpers ----------------
__device__ __forceinline__ uint32_t smem_u32(const void* p){
    uint32_t a; asm("{ .reg .u64 t; cvta.to.shared.u64 t, %1; cvt.u32.u64 %0, t; }":"=r"(a):"l"(p)); return a;
}
__device__ __forceinline__ void cp_async16(uint32_t s, const void* gp){
    uint64_t g = __cvta_generic_to_global(gp);
    asm volatile("cp.async.cg.shared.global [%0], [%1], 16;"::"r"(s),"l"(g));
}
#define CP_COMMIT() asm volatile("cp.async.commit_group;":::"memory")

#define LDSM_X4(r, a) \
    asm volatile("ldmatrix.sync.aligned.m8n8.x4.shared.b16 {%0,%1,%2,%3}, [%4];" \
        : "=r"((r)[0]),"=r"((r)[1]),"=r"((r)[2]),"=r"((r)[3]) : "r"(a))

#define LDSM_X4_T(r, a) \
    asm volatile("ldmatrix.sync.aligned.m8n8.x4.trans.shared.b16 {%0,%1,%2,%3}, [%4];" \
        : "=r"((r)[0]),"=r"((r)[1]),"=r"((r)[2]),"=r"((r)[3]) : "r"(a))

#define MMA_F16(c, a, b0, b1) \
    asm volatile("mma.sync.aligned.m16n8k16.row.col.f32.f16.f16.f32 " \
        "{%0,%1,%2,%3},{%4,%5,%6,%7},{%8,%9},{%0,%1,%2,%3};" \
        : "+f"((c)[0]),"+f"((c)[1]),"+f"((c)[2]),"+f"((c)[3]) \
        : "r"((a)[0]),"r"((a)[1]),"r"((a)[2]),"r"((a)[3]),"r"(b0),"r"(b1))

// ---------------- prep kernels ----------------
__global__ void wg_transpose_kernel(const float* __restrict__ Wg){
    __shared__ float t[32][33];
    int j0 = blockIdx.x*32, s0 = blockIdx.y*32;
    int tx = threadIdx.x, ty = threadIdx.y;
    #pragma unroll
    for(int r=ty; r<32; r+=8)
        t[r][tx] = (s0+tx < NSK) ? Wg[(size_t)(j0+r)*NSK + s0+tx] : 0.f;
    __syncthreads();
    #pragma unroll
    for(int r=ty; r<32; r+=8)
        if(s0+r < NSK) g_Wgt[(size_t)(s0+r)*DIM + j0+tx] = t[tx][r];
}

__global__ void convert_w_kernel(const float* __restrict__ W1, const float* __restrict__ W2){
    const float* src = blockIdx.y ? W2 : W1;
    __half* dst = blockIdx.y ? g_W2h : g_W1h;
    size_t base = (size_t)blockIdx.x*2048 + (size_t)threadIdx.x*8;
    float4 a = *(const float4*)(src + base);
    float4 b = *(const float4*)(src + base + 4);
    __half2 h[4];
    h[0] = __floats2half2_rn(a.x, a.y); h[1] = __floats2half2_rn(a.z, a.w);
    h[2] = __floats2half2_rn(b.x, b.y); h[3] = __floats2half2_rn(b.z, b.w);
    *(uint4*)(dst + base) = *(uint4*)h;
}

__global__ void gates_kernel(const float* __restrict__ x, const float* __restrict__ bg){
    int n = blockIdx.x, tid = threadIdx.x;   // 256 threads
    __shared__ float xs[DIM]; __shared__ float raw[64]; __shared__ float ssum;
    for(int j=tid; j<DIM; j+=256){
        float v = x[(size_t)n*DIM + j];
        xs[j] = v;
        g_Xh[(size_t)n*DIM + j] = __float2half_rn(v);
    }
    __syncthreads();
    int wid = tid>>5, lid = tid&31;
    for(int s=wid; s<NSK; s+=8){
        float acc = 0.f;
        #pragma unroll 8
        for(int j=lid; j<DIM; j+=32) acc += xs[j]*g_Wgt[(size_t)s*DIM + j];
        #pragma unroll
        for(int o=16;o;o>>=1) acc += __shfl_xor_sync(0xFFFFFFFFu, acc, o);
        if(lid==0) raw[s] = acc + bg[s];
    }
    __syncthreads();
    if(tid==0){
        float m = -1e30f;
        for(int s=0;s<NSK;s++) m = fmaxf(m, raw[s]);
        float sm = 0.f;
        for(int s=0;s<NSK;s++){ float e = __expf(raw[s]-m); raw[s]=e; sm+=e; }
        ssum = sm;
    }
    __syncthreads();
    if(tid<NSK) g_gates[(size_t)n*NSK + tid] = raw[tid]/ssum;
}

// final reduce: out = p0+p1+p2+p3 (fixed order, deterministic)
__global__ void reduce_kernel(float* __restrict__ out){
    size_t i = ((size_t)blockIdx.x*256 + threadIdx.x)*4;
    const size_t S = (size_t)NTOK*DIM;
    float4 a = *(const float4*)(g_part + i);
    float4 b = *(const float4*)(g_part + S + i);
    float4 c = *(const float4*)(g_part + 2*S + i);
    float4 d = *(const float4*)(g_part + 3*S + i);
    a.x = (a.x + b.x) + (c.x + d.x);
    a.y = (a.y + b.y) + (c.y + d.y);
    a.z = (a.z + b.z) + (c.z + d.z);
    a.w = (a.w + b.w) + (c.w + d.w);
    *(float4*)(out + i) = a;
}

// ---------------- main fp16 mma.sync GEMM ----------------
// 4 warps (128 thr), warp grid 2x2, warp tile 64x64, 2 CTAs/SM.
// PHASE 1: grid (32,8,50), full K=1024.
// PHASE 2: grid (32,8,NSPLIT), each z does 200 of 800 K-steps -> g_part[z];
//          z==0 adds the gate*b2 prologue.
template<int PHASE>
__global__ void __launch_bounds__(128,2) gemm_kernel(const float* __restrict__ b1,
                                                     const float* __restrict__ b2,
                                                     float* __restrict__ dout){
    extern __shared__ char dsm[];
    const uint32_t sb = (smem_u32(dsm) + 1023u) & ~1023u;
    const uint32_t A0 = sb, B0 = sb + NSTAGE*A_BYTES;
    const int tid = threadIdx.x, wid = tid>>5, lane = tid&31;
    const int wm = wid & 1, wn = wid >> 1;            // 2x2 warp grid
    const int m0 = blockIdx.x*BM, n0 = blockIdx.y*BN;
    const int SPS = NSK*DIM/BK/NSPLIT;                // 200 steps per split
    const int s0step = (PHASE==1) ? 0 : blockIdx.z*SPS;
    const int NS = (PHASE==1) ? (DIM/BK) : SPS;       // 16 / 200

    const int mat = lane>>3, rr = lane&7;
    const int a_rowl = (mat&1)*8 + rr;
    const int a_bc   = (mat>>1)*16;
    const uint32_t xorv = (uint32_t)(rr<<4);
    const int b_row  = lane & 15;
    const int b_noff = (lane >> 4) * 16;
    const int gr = lane>>2, gc = (lane&3)*2;

    float c[4][8][4];
    #pragma unroll
    for(int i=0;i<4;i++)
      #pragma unroll
      for(int j=0;j<8;j++)
        #pragma unroll
        for(int k=0;k<4;k++) c[i][j][k] = 0.f;

    auto load_tile = [&](int step){
        const __half *Ag, *Bg;
        if(PHASE==1){
            int e = blockIdx.z, kk = step*BK;
            Ag = g_Xh  + (size_t)m0*DIM + kk;
            Bg = g_W1h + (size_t)e*DIM*DIM + (size_t)kk*DIM + n0;
        } else {
            int gs = s0step + step;
            int e = gs>>4, kk = (gs&15)*BK;
            Ag = g_Hh  + ((size_t)e*NTOK + m0)*DIM + kk;
            Bg = g_W2h + (size_t)e*DIM*DIM + (size_t)kk*DIM + n0;
        }
        int stg = step % NSTAGE;
        uint32_t as = A0 + stg*A_BYTES, bs = B0 + stg*B_BYTES;
        #pragma unroll
        for(int i=0;i<8;i++){ int q = tid + i*128; int r=q>>3, cc=q&7;
            cp_async16(as + (uint32_t)(r*128 + ((cc*16) ^ ((r&7)<<4))), Ag + (size_t)r*DIM + cc*8); }
        #pragma unroll
        for(int i=0;i<8;i++){ int q = tid + i*128; int r=q>>4, cc=q&15;
            cp_async16(bs + (uint32_t)(r*256 + ((cc*16) ^ ((r&7)<<4))), Bg + (size_t)r*DIM + cc*8); }
        CP_COMMIT();
    };

    load_tile(0); load_tile(1);

    // split 0 prologue (overlapped with fill): c = sum_e gates*b2
    if(PHASE==2 && blockIdx.z==0){
        for(int e=0; e<NSK; e++){
            float gg[4][2];
            #pragma unroll
            for(int mi=0; mi<4; mi++)
                #pragma unroll
                for(int half=0; half<2; half++)
                    gg[mi][half] = g_gates[(size_t)(m0 + wm*64 + mi*16 + gr + half*8)*NSK + e];
            #pragma unroll
            for(int ni=0; ni<8; ni++){
                const float2 bb = *(const float2*)(b2 + (size_t)e*DIM + n0 + wn*64 + ni*8 + gc);
                #pragma unroll
                for(int mi=0; mi<4; mi++)
                    #pragma unroll
                    for(int half=0; half<2; half++){
                        c[mi][ni][half*2+0] += gg[mi][half]*bb.x;
                        c[mi][ni][half*2+1] += gg[mi][half]*bb.y;
                    }
            }
        }
    }

    for(int step=0; step<NS; step++){
        if(step < NS-1) asm volatile("cp.async.wait_group 1;":::"memory");
        else            asm volatile("cp.async.wait_group 0;":::"memory");
        __syncthreads();
        if(step+2 < NS) load_tile(step+2);

        int stg = step % NSTAGE;
        const uint32_t as = A0 + stg*A_BYTES;
        const uint32_t bs = B0 + stg*B_BYTES;
        #pragma unroll
        for(int ks=0; ks<4; ks++){
            uint32_t a[4][4], b[4][4];
            #pragma unroll
            for(int mi=0; mi<4; mi++){
                int row = wm*64 + mi*16 + a_rowl;
                LDSM_X4(a[mi], as + (uint32_t)(row*128) + (((uint32_t)(ks*32 + a_bc)) ^ xorv));
            }
            #pragma unroll
            for(int p=0; p<4; p++){
                int rowk = ks*16 + b_row;
                uint32_t bcol = (uint32_t)(wn*128 + p*32 + b_noff);
                LDSM_X4_T(b[p], bs + (uint32_t)(rowk*256) + (bcol ^ (uint32_t)((rowk&7)<<4)));
            }
            #pragma unroll
            for(int mi=0; mi<4; mi++)
                #pragma unroll
                for(int ni=0; ni<8; ni++)
                    MMA_F16(c[mi][ni], a[mi], b[ni>>1][(ni&1)*2], b[ni>>1][(ni&1)*2+1]);
        }
    }
    __syncthreads();

    if(PHASE==1){
        __half* hs = (__half*)(dsm + (sb - smem_u32(dsm)));
        int e = blockIdx.z;
        #pragma unroll
        for(int mi=0; mi<4; mi++){
            #pragma unroll
            for(int half=0; half<2; half++){
                int row = wm*64 + mi*16 + gr + half*8;
                float gate = g_gates[(size_t)(m0+row)*NSK + e];
                #pragma unroll
                for(int ni=0; ni<8; ni++){
                    int col = wn*64 + ni*8 + gc;
                    const float2 bb = *(const float2*)(b1 + (size_t)e*DIM + n0 + col);
                    float o0 = fmaxf(c[mi][ni][half*2+0] + bb.x, 0.f)*gate;
                    float o1 = fmaxf(c[mi][ni][half*2+1] + bb.y, 0.f)*gate;
                    *(__half2*)(hs + (size_t)row*EPIT + col) = __floats2half2_rn(o0, o1);
                }
            }
        }
        __syncthreads();
        #pragma unroll
        for(int pass=0; pass<16; pass++){
            int q = tid + pass*128;
            int row = q >> 4, ch = q & 15;
            uint4 v = *(const uint4*)(hs + (size_t)row*EPIT + ch*8);
            *(uint4*)(g_Hh + ((size_t)e*NTOK + m0 + row)*DIM + n0 + ch*8) = v;
        }
    } else {
        float* pout = g_part + (size_t)blockIdx.z*NTOK*DIM;
        #pragma unroll
        for(int mi=0; mi<4; mi++){
            int r0 = m0 + wm*64 + mi*16 + gr;
            #pragma unroll
            for(int half=0; half<2; half++){
                int row = r0 + half*8;
                #pragma unroll
                for(int ni=0; ni<8; ni++){
                    int col = n0 + wn*64 + ni*8 + gc;
                    *(float2*)(pout + (size_t)row*DIM + col) =
                        make_float2(c[mi][ni][half*2+0], c[mi][ni][half*2+1]);
                }
            }
        }
    }
}

// ---------------- launch ----------------
extern "C" void kernel_launch(void* const* d_in, const int* in_sizes, int n_in,
                              void* d_out, int out_size){
    const float* x  = (const float*)d_in[0];
    const float* W1 = (const float*)d_in[1];
    const float* b1 = (const float*)d_in[2];
    const float* W2 = (const float*)d_in[3];
    const float* b2 = (const float*)d_in[4];
    const float* Wg = (const float*)d_in[5];
    const float* bg = (const float*)d_in[6];
    float* out = (float*)d_out;

    cudaFuncSetAttribute(gemm_kernel<1>, cudaFuncAttributeMaxDynamicSharedMemorySize, SMEM_DYN);
    cudaFuncSetAttribute(gemm_kernel<2>, cudaFuncAttributeMaxDynamicSharedMemorySize, SMEM_DYN);

    wg_transpose_kernel<<<dim3(32, 2), dim3(32, 8)>>>(Wg);
    gates_kernel<<<NTOK, 256>>>(x, bg);
    convert_w_kernel<<<dim3(25600, 2), 256>>>(W1, W2);
    gemm_kernel<1><<<dim3(NTOK/BM, DIM/BN, NSK), 128, SMEM_DYN>>>(b1, nullptr, nullptr);
    gemm_kernel<2><<<dim3(NTOK/BM, DIM/BN, NSPLIT), 128, SMEM_DYN>>>(nullptr, b2, nullptr);
    reduce_kernel<<<NTOK*DIM/1024, 256>>>(out);
}